// round 15
// baseline (speedup 1.0000x reference)
#include <cuda_runtime.h>
#include <cuda_fp16.h>
#include <cstdint>
#include <math.h>

#define BATCH 128
#define TTOK  64
#define ITOK  196
#define DIM   512
#define TEMP  0.07f

#define MROWS 128
#define NCHUNK 8
#define NTHREADS 512
#define NSTAGE 3
#define QMAX 4096
#define NTILES 8192
#define STRIDE 148            // persistent grid size

// per-stage smem (bytes): A 128 rows x 128B + B 200 rows x 128B, SW128-swizzled
#define AHI 0
#define BHI 16384
#define STAGE 41984
#define SMEM_BYTES (NSTAGE * STAGE)   // 125952

__device__ __align__(16) __half g_text_hi[BATCH * TTOK * DIM];
__device__ __align__(16) __half g_img_hi[BATCH * ITOK * DIM + 4 * DIM]; // +4 pad rows
__device__ float g_S[BATCH * BATCH];
__device__ float g_maxnorm[2];   // [0]=text, [1]=image

// ---------------- helpers ----------------
__device__ __forceinline__ uint32_t smem_u32(const void* p) {
    uint32_t a;
    asm("{ .reg .u64 t; cvta.to.shared.u64 t, %1; cvt.u32.u64 %0, t; }" : "=r"(a) : "l"(p));
    return a;
}
__device__ __forceinline__ uint32_t sw_off(int row, int koff) {
    return (uint32_t)(row * 128 + (koff ^ ((row & 7) << 4)));
}
__device__ __forceinline__ void cp16(uint32_t dst, const void* src) {
    asm volatile("cp.async.cg.shared.global [%0], [%1], 16;" :: "r"(dst), "l"(src) : "memory");
}
#define CP_COMMIT() asm volatile("cp.async.commit_group;" ::: "memory")
#define CP_WAIT1()  asm volatile("cp.async.wait_group 1;" ::: "memory")
#define CP_WAIT0()  asm volatile("cp.async.wait_group 0;" ::: "memory")

__device__ __forceinline__ void ldsm_x4(uint32_t (&r)[4], uint32_t addr) {
    asm volatile("ldmatrix.sync.aligned.m8n8.x4.shared.b16 {%0,%1,%2,%3}, [%4];"
                 : "=r"(r[0]), "=r"(r[1]), "=r"(r[2]), "=r"(r[3]) : "r"(addr));
}
__device__ __forceinline__ void ldsm_x2(uint32_t (&r)[2], uint32_t addr) {
    asm volatile("ldmatrix.sync.aligned.m8n8.x2.shared.b16 {%0,%1}, [%2];"
                 : "=r"(r[0]), "=r"(r[1]) : "r"(addr));
}
__device__ __forceinline__ void mma16816(float (&d)[4], const uint32_t (&a)[4],
                                         const uint32_t* b) {
    asm volatile(
        "mma.sync.aligned.m16n8k16.row.col.f32.f16.f16.f32 "
        "{%0,%1,%2,%3}, {%4,%5,%6,%7}, {%8,%9}, {%0,%1,%2,%3};"
        : "+f"(d[0]), "+f"(d[1]), "+f"(d[2]), "+f"(d[3])
        : "r"(a[0]), "r"(a[1]), "r"(a[2]), "r"(a[3]), "r"(b[0]), "r"(b[1]));
}
__device__ __forceinline__ unsigned ford(float f) {
    unsigned b = __float_as_uint(f);
    return (b & 0x80000000u) ? ~b : (b | 0x80000000u);
}
__device__ __forceinline__ float funord(unsigned u) {
    return __uint_as_float((u & 0x80000000u) ? (u & 0x7FFFFFFFu) : ~u);
}

// ---------------- init ----------------
__global__ void init_kernel() {
    if (threadIdx.x == 0) { g_maxnorm[0] = 0.0f; g_maxnorm[1] = 0.0f; }
    for (int i = threadIdx.x; i < 4 * DIM; i += blockDim.x)
        g_img_hi[BATCH * ITOK * DIM + i] = __ushort_as_half((unsigned short)0);
}

// ---------------- fused f32->fp16 convert + per-row norm + global max -------
__global__ void convert_norm(const float* __restrict__ src, __half* __restrict__ hi,
                             int nrows, int slot) {
    __shared__ float s_part[4][4];
    const int w = threadIdx.x >> 5, l = threadIdx.x & 31;
    const int rg = w >> 2, wg = w & 3;
    const int row = blockIdx.x * 4 + rg;
    const int t = threadIdx.x & 127;
    if (row >= nrows) return;

    float4 v = ((const float4*)(src + (size_t)row * DIM))[t];
    ushort4 h;
    h.x = __half_as_ushort(__float2half_rn(v.x));
    h.y = __half_as_ushort(__float2half_rn(v.y));
    h.z = __half_as_ushort(__float2half_rn(v.z));
    h.w = __half_as_ushort(__float2half_rn(v.w));
    ((ushort4*)(hi + (size_t)row * DIM))[t] = h;

    float s = v.x * v.x + v.y * v.y + v.z * v.z + v.w * v.w;
#pragma unroll
    for (int off = 16; off > 0; off >>= 1)
        s += __shfl_xor_sync(0xffffffffu, s, off);
    if (l == 0) s_part[rg][wg] = s;
    __syncthreads();
    if (t == 0) {
        float tot = s_part[rg][0] + s_part[rg][1] + s_part[rg][2] + s_part[rg][3];
        atomicMax((int*)&g_maxnorm[slot], __float_as_int(sqrtf(tot)));
    }
}

// ---------------- chunk loader (tile-aware) ----------------
__device__ __forceinline__ void load_chunk(uint32_t su_s, int tile, int ch, int tid) {
    const uint4* thi = (const uint4*)g_text_hi;
    const uint4* ihi = (const uint4*)g_img_hi;
    const int trow0 = (tile & 63) * MROWS;
    const int irow0 = (tile >> 6) * ITOK;
#pragma unroll
    for (int idx = tid; idx < 1024; idx += NTHREADS) {   // A: 128 rows x 8 chunks
        int r = idx >> 3, kq = idx & 7;
        cp16(su_s + AHI + sw_off(r, kq * 16),
             thi + (size_t)(trow0 + r) * 64 + ch * 8 + kq);
    }
#pragma unroll
    for (int idx = tid; idx < 1600; idx += NTHREADS) {   // B: 200 rows x 8 chunks
        int r = idx >> 3, kq = idx & 7;
        cp16(su_s + BHI + sw_off(r, kq * 16),
             ihi + (size_t)(irow0 + r) * 64 + ch * 8 + kq);
    }
}

// ---------------- per-chunk compute (1 term, 2 m-tiles) ----------------
template <int NT>
__device__ __forceinline__ void compute_chunk(
    uint32_t sa, uint32_t sb, int a_row, int a_kl, int b_prow, int b_kl,
    int b_lrow, float (&acc)[2][7][4]) {
#pragma unroll
    for (int ks = 0; ks < 4; ++ks) {
        const int koff = ks * 32;
        uint32_t aH[2][4];
#pragma unroll
        for (int mt = 0; mt < 2; ++mt)
            ldsm_x4(aH[mt], sa + sw_off(a_row + mt * 16, koff + a_kl));
#pragma unroll
        for (int p = 0; p < NT / 2; ++p) {
            uint32_t bh[4];
            ldsm_x4(bh, sb + sw_off(b_prow + p * 16, koff + b_kl));
#pragma unroll
            for (int mt = 0; mt < 2; ++mt) {
                mma16816(acc[mt][2 * p],     aH[mt], bh + 0);
                mma16816(acc[mt][2 * p + 1], aH[mt], bh + 2);
            }
        }
        if (NT & 1) {
            uint32_t bh[2];
            ldsm_x2(bh, sb + sw_off(b_lrow, koff + b_kl));
#pragma unroll
            for (int mt = 0; mt < 2; ++mt)
                mma16816(acc[mt][NT - 1], aH[mt], bh);
        }
    }
}

// ---------------- persistent maxsim kernel ----------------
// grid = 148 CTAs; each walks tiles t = blockIdx.x, +148, ... over 8192 tiles.
// Cross-tile chunk pipeline: load for global chunk g+2 issued while computing g,
// including across tile boundaries -> no per-tile prologue; epilogue overlaps
// with next tile's loads. 512 threads = 16 warps; w_m = w & 3 (SMSP-balanced).
__global__ __launch_bounds__(NTHREADS, 1)
void maxsim_kernel(const float* __restrict__ imgf, const float* __restrict__ textf) {
    extern __shared__ __align__(1024) char smem[];
    __shared__ float s_nmax[4][MROWS];
    __shared__ float s_thr[MROWS];
    __shared__ unsigned s_exact[MROWS];
    __shared__ int s_queue[QMAX];
    __shared__ int s_qcount;
    __shared__ float s_red[4];

    const int tid = threadIdx.x;
    const uint32_t su = smem_u32(smem);
    const int w = tid >> 5, l = tid & 31;
    const int w_m = w & 3, w_n = w >> 2;

    const int a_row  = w_m * 32 + (l & 15);
    const int a_kl   = (l >> 4) * 16;
    const int b_prow = w_n * 56 + ((l >> 4) << 3) + (l & 7);
    const int b_kl   = ((l >> 3) & 1) * 16;
    const int b_lrow = w_n * 56 + 48 + (l & 7);
    const int NTa = (w_n == 3) ? 4 : 7;

    int t = blockIdx.x;
    // prologue for the first tile only
    load_chunk(su + 0 * STAGE, t, 0, tid);
    CP_COMMIT();
    load_chunk(su + 1 * STAGE, t, 1, tid);
    CP_COMMIT();
    int sc = 0;   // stage of the next chunk to compute

    for (; t < NTILES; t += STRIDE) {
        const int trow0 = (t & 63) * MROWS;
        const int b2 = t >> 6;
        const int irow0 = b2 * ITOK;

        float acc[2][7][4];
#pragma unroll
        for (int a = 0; a < 2; ++a)
#pragma unroll
            for (int b = 0; b < 7; ++b)
#pragma unroll
                for (int c = 0; c < 4; ++c) acc[a][b][c] = 0.0f;

        for (int ch = 0; ch < NCHUNK; ++ch) {
            // next chunk (g+1) exists unless this is the very last chunk overall
            const bool last = (ch == NCHUNK - 1) && (t + STRIDE >= NTILES);
            if (last) CP_WAIT0(); else CP_WAIT1();
            __syncthreads();
            // issue load for g+2 (may belong to the next tile)
            int c2 = ch + 2, t2 = t;
            if (c2 >= NCHUNK) { c2 -= NCHUNK; t2 += STRIDE; }
            if (t2 < NTILES) {
                load_chunk(su + ((sc + 2) % NSTAGE) * STAGE, t2, c2, tid);
                CP_COMMIT();
            }
            const uint32_t sb = su + sc * STAGE;
            sc = (sc + 1) % NSTAGE;
            if (w_n == 3)
                compute_chunk<4>(sb + AHI, sb + BHI, a_row, a_kl, b_prow, b_kl, b_lrow, acc);
            else
                compute_chunk<7>(sb + AHI, sb + BHI, a_row, a_kl, b_prow, b_kl, b_lrow, acc);
        }

        // ---- epilogue (next tile's chunk 0/1 loads are in flight) ----
        // phase 2a: row max from registers (mask cols >= 196)
        float rm[2][2];
        rm[0][0] = rm[0][1] = rm[1][0] = rm[1][1] = -INFINITY;
#pragma unroll
        for (int mt = 0; mt < 2; ++mt)
            for (int nt = 0; nt < 7; ++nt) {
                if (nt >= NTa) break;
#pragma unroll
                for (int h = 0; h < 2; ++h)
#pragma unroll
                    for (int j = 0; j < 2; ++j) {
                        int col = w_n * 56 + nt * 8 + (l & 3) * 2 + j;
                        if (col < ITOK)
                            rm[mt][h] = fmaxf(rm[mt][h], acc[mt][nt][h * 2 + j]);
                    }
            }
#pragma unroll
        for (int off = 1; off <= 2; off <<= 1)
#pragma unroll
            for (int mt = 0; mt < 2; ++mt)
#pragma unroll
                for (int h = 0; h < 2; ++h)
                    rm[mt][h] = fmaxf(rm[mt][h], __shfl_xor_sync(0xffffffffu, rm[mt][h], off));
        __syncthreads();   // prior tile's phase2c done reading s_queue / s_exact
        if (tid == 0) s_qcount = 0;
        if (tid < MROWS) s_exact[tid] = 0u;
        if ((l & 3) == 0) {
#pragma unroll
            for (int mt = 0; mt < 2; ++mt)
#pragma unroll
                for (int h = 0; h < 2; ++h)
                    s_nmax[w_n][w_m * 32 + mt * 16 + (l >> 2) + h * 8] = rm[mt][h];
        }
        __syncthreads();

        const float margin = ldexpf(g_maxnorm[0] * g_maxnorm[1], -10) + 0.03f;
        if (tid < MROWS) {
            float m = fmaxf(fmaxf(s_nmax[0][tid], s_nmax[1][tid]),
                            fmaxf(s_nmax[2][tid], s_nmax[3][tid]));
            s_thr[tid] = m - 2.0f * margin;
        }
        __syncthreads();

        // phase 2b: candidate detection from registers
#pragma unroll
        for (int mt = 0; mt < 2; ++mt)
            for (int nt = 0; nt < 7; ++nt) {
                if (nt >= NTa) break;
#pragma unroll
                for (int h = 0; h < 2; ++h) {
                    int row = w_m * 32 + mt * 16 + (l >> 2) + h * 8;
                    float thr = s_thr[row];
#pragma unroll
                    for (int j = 0; j < 2; ++j) {
                        int col = w_n * 56 + nt * 8 + (l & 3) * 2 + j;
                        if (col < ITOK && acc[mt][nt][h * 2 + j] >= thr) {
                            int pos = atomicAdd(&s_qcount, 1);
                            if (pos < QMAX) s_queue[pos] = (row << 8) | col;
                        }
                    }
                }
            }
        __syncthreads();

        const int qtotal = s_qcount;
        const int qn = qtotal < QMAX ? qtotal : QMAX;

        // phase 2c: exact rescore, 16 warps drain queue with prefetch
        {
            float4 TA[4], IA[4], TB[4], IB[4];
            int rowA = 0, rowB = 0;
            int qi = w;
            bool haveA = (qi < qn);
            if (haveA) {
                int e = s_queue[qi];
                rowA = e >> 8;
                const float4* tp = (const float4*)(textf + (size_t)(trow0 + rowA) * DIM);
                const float4* ip = (const float4*)(imgf + ((size_t)b2 * ITOK + (e & 255)) * DIM);
#pragma unroll
                for (int q = 0; q < 4; ++q) { TA[q] = tp[q * 32 + l]; IA[q] = ip[q * 32 + l]; }
            }
            while (haveA) {
                int qj = qi + 16;
                bool haveB = (qj < qn);
                if (haveB) {
                    int e = s_queue[qj];
                    rowB = e >> 8;
                    const float4* tp = (const float4*)(textf + (size_t)(trow0 + rowB) * DIM);
                    const float4* ip = (const float4*)(imgf + ((size_t)b2 * ITOK + (e & 255)) * DIM);
#pragma unroll
                    for (int q = 0; q < 4; ++q) { TB[q] = tp[q * 32 + l]; IB[q] = ip[q * 32 + l]; }
                }
                float s = 0.0f;
#pragma unroll
                for (int q = 0; q < 4; ++q) {
                    s = fmaf(TA[q].x, IA[q].x, s);
                    s = fmaf(TA[q].y, IA[q].y, s);
                    s = fmaf(TA[q].z, IA[q].z, s);
                    s = fmaf(TA[q].w, IA[q].w, s);
                }
#pragma unroll
                for (int off = 16; off > 0; off >>= 1)
                    s += __shfl_xor_sync(0xffffffffu, s, off);
                if (l == 0) atomicMax(&s_exact[rowA], ford(s));
                qi = qj; haveA = haveB;
                if (haveB) {
                    rowA = rowB;
#pragma unroll
                    for (int q = 0; q < 4; ++q) { TA[q] = TB[q]; IA[q] = IB[q]; }
                }
            }
        }

        // fallback (never expected): full exact recompute per row
        if (qtotal > QMAX) {
            for (int row = w; row < MROWS; row += 16) {
                const float4* tp = (const float4*)(textf + (size_t)(trow0 + row) * DIM);
                float4 ta[4];
#pragma unroll
                for (int q = 0; q < 4; ++q) ta[q] = tp[q * 32 + l];
                float emax = -INFINITY;
                for (int j = 0; j < ITOK; ++j) {
                    const float4* ip = (const float4*)(imgf + ((size_t)b2 * ITOK + j) * DIM);
                    float s = 0.0f;
#pragma unroll
                    for (int q = 0; q < 4; ++q) {
                        float4 iv = ip[q * 32 + l];
                        s = fmaf(ta[q].x, iv.x, s);
                        s = fmaf(ta[q].y, iv.y, s);
                        s = fmaf(ta[q].z, iv.z, s);
                        s = fmaf(ta[q].w, iv.w, s);
                    }
#pragma unroll
                    for (int off = 16; off > 0; off >>= 1)
                        s += __shfl_xor_sync(0xffffffffu, s, off);
                    emax = fmaxf(emax, s);
                }
                if (l == 0) atomicMax(&s_exact[row], ford(emax));
            }
        }
        __syncthreads();

        // mean over text rows -> g_S
        if (tid < MROWS) {
            float m = funord(s_exact[tid]);
#pragma unroll
            for (int off = 16; off > 0; off >>= 1)
                m += __shfl_xor_sync(0xffffffffu, m, off);
            if ((tid & 31) == 0) s_red[tid >> 5] = m;
        }
        __syncthreads();
        if (tid == 0) {
            const int mtile = t & 63;
            g_S[(mtile * 2 + 0) * BATCH + b2] = (s_red[0] + s_red[1]) * (1.0f / TTOK);
            g_S[(mtile * 2 + 1) * BATCH + b2] = (s_red[2] + s_red[3]) * (1.0f / TTOK);
        }
    }
}

// ---------------- symmetric InfoNCE ----------------
__global__ void loss_kernel(float* __restrict__ out) {
    __shared__ float s_red[BATCH];
    __shared__ float s_fin[4];
    const int tid = threadIdx.x;
    const int b = tid >> 3, s = tid & 7;
    const float invT = 1.0f / TEMP;

    float rv[16], cv[16];
#pragma unroll
    for (int j = 0; j < 16; ++j) {
        int jj = s * 16 + j;
        rv[j] = g_S[b * BATCH + jj];
        cv[j] = g_S[jj * BATCH + b];
    }
    float rmax = -INFINITY, cmax = -INFINITY;
#pragma unroll
    for (int j = 0; j < 16; ++j) {
        rmax = fmaxf(rmax, rv[j]);
        cmax = fmaxf(cmax, cv[j]);
    }
#pragma unroll
    for (int off = 1; off <= 4; off <<= 1) {
        rmax = fmaxf(rmax, __shfl_xor_sync(0xffffffffu, rmax, off));
        cmax = fmaxf(cmax, __shfl_xor_sync(0xffffffffu, cmax, off));
    }
    float rs = 0.0f, cs = 0.0f;
#pragma unroll
    for (int j = 0; j < 16; ++j) {
        rs += expf((rv[j] - rmax) * invT);
        cs += expf((cv[j] - cmax) * invT);
    }
#pragma unroll
    for (int off = 1; off <= 4; off <<= 1) {
        rs += __shfl_xor_sync(0xffffffffu, rs, off);
        cs += __shfl_xor_sync(0xffffffffu, cs, off);
    }
    if (s == 0) {
        float diag = g_S[b * BATCH + b] * invT;
        float rlse = rmax * invT + logf(rs);
        float clse = cmax * invT + logf(cs);
        s_red[b] = 0.5f * ((rlse - diag) + (clse - diag));
    }
    __syncthreads();
    if (tid < 128) {
        float v = s_red[tid];
#pragma unroll
        for (int off = 16; off > 0; off >>= 1)
            v += __shfl_xor_sync(0xffffffffu, v, off);
        if ((tid & 31) == 0) s_fin[tid >> 5] = v;
    }
    __syncthreads();
    if (tid == 0)
        out[0] = (s_fin[0] + s_fin[1] + s_fin[2] + s_fin[3]) * (1.0f / BATCH);
}

extern "C" void kernel_launch(void* const* d_in, const int* in_sizes, int n_in,
                              void* d_out, int out_size) {
    const float* image = (const float*)d_in[0];   // [128, 196, 512]
    const float* text  = (const float*)d_in[1];   // [128,  64, 512]

    __half *thi, *ihi;
    cudaGetSymbolAddress((void**)&thi, g_text_hi);
    cudaGetSymbolAddress((void**)&ihi, g_img_hi);

    init_kernel<<<1, 256>>>();
    convert_norm<<<BATCH * TTOK / 4, 512>>>(text, thi, BATCH * TTOK, 0);
    convert_norm<<<BATCH * ITOK / 4, 512>>>(image, ihi, BATCH * ITOK, 1);

    cudaFuncSetAttribute(maxsim_kernel,
                         cudaFuncAttributeMaxDynamicSharedMemorySize, SMEM_BYTES);
    maxsim_kernel<<<STRIDE, NTHREADS, SMEM_BYTES>>>(image, text);

    loss_kernel<<<1, 1024>>>((float*)d_out);
}

// round 16
// speedup vs baseline: 1.4993x; 1.4993x over previous
#include <cuda_runtime.h>
#include <cuda_fp16.h>
#include <cstdint>
#include <math.h>

#define BATCH 128
#define TTOK  64
#define ITOK  196
#define DIM   512
#define TEMP  0.07f

#define MROWS 128
#define NIT   4               // 4 double-chunks of K=128
#define NTHREADS 512
#define QMAX 4096

// sub-chunk smem (bytes): A 128 rows x 128B + B 200 rows x 128B, SW128-swizzled
#define AHI 0
#define BHI 16384
#define SUB 41984
#define STAGE (2 * SUB)            // 83968 (double chunk)
#define SMEM_BYTES (2 * STAGE)     // 167936

__device__ __align__(16) __half g_text_hi[BATCH * TTOK * DIM];
__device__ __align__(16) __half g_img_hi[BATCH * ITOK * DIM + 4 * DIM]; // +4 pad rows
__device__ float g_S[BATCH * BATCH];
__device__ float g_maxnorm[2];   // [0]=text, [1]=image

// ---------------- helpers ----------------
__device__ __forceinline__ uint32_t smem_u32(const void* p) {
    uint32_t a;
    asm("{ .reg .u64 t; cvta.to.shared.u64 t, %1; cvt.u32.u64 %0, t; }" : "=r"(a) : "l"(p));
    return a;
}
__device__ __forceinline__ uint32_t sw_off(int row, int koff) {
    return (uint32_t)(row * 128 + (koff ^ ((row & 7) << 4)));
}
__device__ __forceinline__ void cp16(uint32_t dst, const void* src) {
    asm volatile("cp.async.cg.shared.global [%0], [%1], 16;" :: "r"(dst), "l"(src) : "memory");
}
#define CP_COMMIT() asm volatile("cp.async.commit_group;" ::: "memory")
#define CP_WAIT0()  asm volatile("cp.async.wait_group 0;" ::: "memory")

__device__ __forceinline__ void ldsm_x4(uint32_t (&r)[4], uint32_t addr) {
    asm volatile("ldmatrix.sync.aligned.m8n8.x4.shared.b16 {%0,%1,%2,%3}, [%4];"
                 : "=r"(r[0]), "=r"(r[1]), "=r"(r[2]), "=r"(r[3]) : "r"(addr));
}
__device__ __forceinline__ void ldsm_x2(uint32_t (&r)[2], uint32_t addr) {
    asm volatile("ldmatrix.sync.aligned.m8n8.x2.shared.b16 {%0,%1}, [%2];"
                 : "=r"(r[0]), "=r"(r[1]) : "r"(addr));
}
__device__ __forceinline__ void mma16816(float (&d)[4], const uint32_t (&a)[4],
                                         const uint32_t* b) {
    asm volatile(
        "mma.sync.aligned.m16n8k16.row.col.f32.f16.f16.f32 "
        "{%0,%1,%2,%3}, {%4,%5,%6,%7}, {%8,%9}, {%0,%1,%2,%3};"
        : "+f"(d[0]), "+f"(d[1]), "+f"(d[2]), "+f"(d[3])
        : "r"(a[0]), "r"(a[1]), "r"(a[2]), "r"(a[3]), "r"(b[0]), "r"(b[1]));
}
__device__ __forceinline__ unsigned ford(float f) {
    unsigned b = __float_as_uint(f);
    return (b & 0x80000000u) ? ~b : (b | 0x80000000u);
}
__device__ __forceinline__ float funord(unsigned u) {
    return __uint_as_float((u & 0x80000000u) ? (u & 0x7FFFFFFFu) : ~u);
}

// ---------------- init ----------------
__global__ void init_kernel() {
    if (threadIdx.x == 0) { g_maxnorm[0] = 0.0f; g_maxnorm[1] = 0.0f; }
    for (int i = threadIdx.x; i < 4 * DIM; i += blockDim.x)
        g_img_hi[BATCH * ITOK * DIM + i] = __ushort_as_half((unsigned short)0);
}

// ---------------- fused f32->fp16 convert + per-row norm + global max -------
__global__ void convert_norm(const float* __restrict__ src, __half* __restrict__ hi,
                             int nrows, int slot) {
    __shared__ float s_part[4][4];
    const int w = threadIdx.x >> 5, l = threadIdx.x & 31;
    const int rg = w >> 2, wg = w & 3;
    const int row = blockIdx.x * 4 + rg;
    const int t = threadIdx.x & 127;
    if (row >= nrows) return;

    float4 v = ((const float4*)(src + (size_t)row * DIM))[t];
    ushort4 h;
    h.x = __half_as_ushort(__float2half_rn(v.x));
    h.y = __half_as_ushort(__float2half_rn(v.y));
    h.z = __half_as_ushort(__float2half_rn(v.z));
    h.w = __half_as_ushort(__float2half_rn(v.w));
    ((ushort4*)(hi + (size_t)row * DIM))[t] = h;

    float s = v.x * v.x + v.y * v.y + v.z * v.z + v.w * v.w;
#pragma unroll
    for (int off = 16; off > 0; off >>= 1)
        s += __shfl_xor_sync(0xffffffffu, s, off);
    if (l == 0) s_part[rg][wg] = s;
    __syncthreads();
    if (t == 0) {
        float tot = s_part[rg][0] + s_part[rg][1] + s_part[rg][2] + s_part[rg][3];
        atomicMax((int*)&g_maxnorm[slot], __float_as_int(sqrtf(tot)));
    }
}

// ---------------- double-chunk loader: K=128 (two 64-elem sub-chunks) -------
__device__ __forceinline__ void load_chunk2(uint32_t su_s, int it, int tid,
                                            int trow0, int irow0) {
    const uint4* thi = (const uint4*)g_text_hi;
    const uint4* ihi = (const uint4*)g_img_hi;
#pragma unroll
    for (int s = 0; s < 2; ++s) {
        const int ko16 = it * 16 + s * 8;    // 16B-chunk offset in 512-elem row
        const uint32_t base = su_s + s * SUB;
#pragma unroll
        for (int idx = tid; idx < 1024; idx += NTHREADS) {   // A: 128 rows x 8
            int r = idx >> 3, kq = idx & 7;
            cp16(base + AHI + sw_off(r, kq * 16),
                 thi + (size_t)(trow0 + r) * 64 + ko16 + kq);
        }
#pragma unroll
        for (int idx = tid; idx < 1600; idx += NTHREADS) {   // B: 200 rows x 8
            int r = idx >> 3, kq = idx & 7;
            cp16(base + BHI + sw_off(r, kq * 16),
                 ihi + (size_t)(irow0 + r) * 64 + ko16 + kq);
        }
    }
}

// ---------------- per-sub-chunk compute (identical to R12 inner) ------------
template <int NT>
__device__ __forceinline__ void compute_chunk(
    uint32_t sa, uint32_t sb, int a_row, int a_kl, int b_prow, int b_kl,
    int b_lrow, float (&acc)[2][7][4]) {
#pragma unroll
    for (int ks = 0; ks < 4; ++ks) {
        const int koff = ks * 32;
        uint32_t aH[2][4];
#pragma unroll
        for (int mt = 0; mt < 2; ++mt)
            ldsm_x4(aH[mt], sa + sw_off(a_row + mt * 16, koff + a_kl));
#pragma unroll
        for (int p = 0; p < NT / 2; ++p) {
            uint32_t bh[4];
            ldsm_x4(bh, sb + sw_off(b_prow + p * 16, koff + b_kl));
#pragma unroll
            for (int mt = 0; mt < 2; ++mt) {
                mma16816(acc[mt][2 * p],     aH[mt], bh + 0);
                mma16816(acc[mt][2 * p + 1], aH[mt], bh + 2);
            }
        }
        if (NT & 1) {
            uint32_t bh[2];
            ldsm_x2(bh, sb + sw_off(b_lrow, koff + b_kl));
#pragma unroll
            for (int mt = 0; mt < 2; ++mt)
                mma16816(acc[mt][NT - 1], aH[mt], bh);
        }
    }
}

// ---------------- maxsim kernel ----------------
// grid (mtile=64, b2=128); 512 threads = 16 warps; warp tile 32x56.
// SMSP-balanced: w_m = w & 3 (== SMSP id), w_n = w >> 2.
// K processed in 4 double-chunks of 128 -> half the sync/wait events of R12.
__global__ __launch_bounds__(NTHREADS, 1)
void maxsim_kernel(const float* __restrict__ imgf, const float* __restrict__ textf) {
    extern __shared__ __align__(1024) char smem[];
    __shared__ float s_nmax[4][MROWS];
    __shared__ float s_thr[MROWS];
    __shared__ unsigned s_exact[MROWS];
    __shared__ int s_queue[QMAX];
    __shared__ int s_qcount;
    __shared__ float s_red[4];

    const int tid = threadIdx.x;
    const int mtile = blockIdx.x, b2 = blockIdx.y;
    const int trow0 = mtile * MROWS, irow0 = b2 * ITOK;
    const uint32_t su = smem_u32(smem);
    const int w = tid >> 5, l = tid & 31;
    const int w_m = w & 3, w_n = w >> 2;

    const int a_row  = w_m * 32 + (l & 15);
    const int a_kl   = (l >> 4) * 16;
    const int b_prow = w_n * 56 + ((l >> 4) << 3) + (l & 7);
    const int b_kl   = ((l >> 3) & 1) * 16;
    const int b_lrow = w_n * 56 + 48 + (l & 7);

    if (tid == 0) s_qcount = 0;
    if (tid < MROWS) s_exact[tid] = 0u;

    float acc[2][7][4];
#pragma unroll
    for (int a = 0; a < 2; ++a)
#pragma unroll
        for (int b = 0; b < 7; ++b)
#pragma unroll
            for (int c = 0; c < 4; ++c) acc[a][b][c] = 0.0f;

    load_chunk2(su, 0, tid, trow0, irow0);
    CP_COMMIT();

    // 2-stage double-buffer: wait0 -> sync -> issue it+1 -> compute both subs
    for (int it = 0; it < NIT; ++it) {
        CP_WAIT0();
        __syncthreads();
        if (it + 1 < NIT) {
            load_chunk2(su + ((it + 1) & 1) * STAGE, it + 1, tid, trow0, irow0);
            CP_COMMIT();
        }
        const uint32_t st = su + (it & 1) * STAGE;
#pragma unroll
        for (int s = 0; s < 2; ++s) {
            const uint32_t sb = st + s * SUB;
            if (w_n == 3)
                compute_chunk<4>(sb + AHI, sb + BHI, a_row, a_kl, b_prow, b_kl, b_lrow, acc);
            else
                compute_chunk<7>(sb + AHI, sb + BHI, a_row, a_kl, b_prow, b_kl, b_lrow, acc);
        }
    }

    // ---- phase 2a: row max from registers (mask cols >= 196)
    const int NTa = (w_n == 3) ? 4 : 7;
    float rm[2][2];
    rm[0][0] = rm[0][1] = rm[1][0] = rm[1][1] = -INFINITY;
#pragma unroll
    for (int mt = 0; mt < 2; ++mt)
        for (int nt = 0; nt < 7; ++nt) {
            if (nt >= NTa) break;
#pragma unroll
            for (int h = 0; h < 2; ++h)
#pragma unroll
                for (int j = 0; j < 2; ++j) {
                    int col = w_n * 56 + nt * 8 + (l & 3) * 2 + j;
                    if (col < ITOK)
                        rm[mt][h] = fmaxf(rm[mt][h], acc[mt][nt][h * 2 + j]);
                }
        }
#pragma unroll
    for (int off = 1; off <= 2; off <<= 1)
#pragma unroll
        for (int mt = 0; mt < 2; ++mt)
#pragma unroll
            for (int h = 0; h < 2; ++h)
                rm[mt][h] = fmaxf(rm[mt][h], __shfl_xor_sync(0xffffffffu, rm[mt][h], off));
    if ((l & 3) == 0) {
#pragma unroll
        for (int mt = 0; mt < 2; ++mt)
#pragma unroll
            for (int h = 0; h < 2; ++h)
                s_nmax[w_n][w_m * 32 + mt * 16 + (l >> 2) + h * 8] = rm[mt][h];
    }
    __syncthreads();

    // margin: |approx-exact| <= 2^-10 * ||t||max * ||i||max + accum slack
    const float margin = ldexpf(g_maxnorm[0] * g_maxnorm[1], -10) + 0.03f;
    if (tid < MROWS) {
        float m = fmaxf(fmaxf(s_nmax[0][tid], s_nmax[1][tid]),
                        fmaxf(s_nmax[2][tid], s_nmax[3][tid]));
        s_thr[tid] = m - 2.0f * margin;
    }
    __syncthreads();

    // ---- phase 2b: candidate detection from registers
#pragma unroll
    for (int mt = 0; mt < 2; ++mt)
        for (int nt = 0; nt < 7; ++nt) {
            if (nt >= NTa) break;
#pragma unroll
            for (int h = 0; h < 2; ++h) {
                int row = w_m * 32 + mt * 16 + (l >> 2) + h * 8;
                float thr = s_thr[row];
#pragma unroll
                for (int j = 0; j < 2; ++j) {
                    int col = w_n * 56 + nt * 8 + (l & 3) * 2 + j;
                    if (col < ITOK && acc[mt][nt][h * 2 + j] >= thr) {
                        int pos = atomicAdd(&s_qcount, 1);
                        if (pos < QMAX) s_queue[pos] = (row << 8) | col;
                    }
                }
            }
        }
    __syncthreads();

    const int qtotal = s_qcount;
    const int qn = qtotal < QMAX ? qtotal : QMAX;

    // ---- phase 2c: exact rescore, 16 warps drain queue with prefetch
    {
        float4 TA[4], IA[4], TB[4], IB[4];
        int rowA = 0, rowB = 0;
        int qi = w;
        bool haveA = (qi < qn);
        if (haveA) {
            int e = s_queue[qi];
            rowA = e >> 8;
            const float4* tp = (const float4*)(textf + (size_t)(trow0 + rowA) * DIM);
            const float4* ip = (const float4*)(imgf + ((size_t)b2 * ITOK + (e & 255)) * DIM);
#pragma unroll
            for (int q = 0; q < 4; ++q) { TA[q] = tp[q * 32 + l]; IA[q] = ip[q * 32 + l]; }
        }
        while (haveA) {
            int qj = qi + 16;
            bool haveB = (qj < qn);
            if (haveB) {
                int e = s_queue[qj];
                rowB = e >> 8;
                const float4* tp = (const float4*)(textf + (size_t)(trow0 + rowB) * DIM);
                const float4* ip = (const float4*)(imgf + ((size_t)b2 * ITOK + (e & 255)) * DIM);
#pragma unroll
                for (int q = 0; q < 4; ++q) { TB[q] = tp[q * 32 + l]; IB[q] = ip[q * 32 + l]; }
            }
            float s = 0.0f;
#pragma unroll
            for (int q = 0; q < 4; ++q) {
                s = fmaf(TA[q].x, IA[q].x, s);
                s = fmaf(TA[q].y, IA[q].y, s);
                s = fmaf(TA[q].z, IA[q].z, s);
                s = fmaf(TA[q].w, IA[q].w, s);
            }
#pragma unroll
            for (int off = 16; off > 0; off >>= 1)
                s += __shfl_xor_sync(0xffffffffu, s, off);
            if (l == 0) atomicMax(&s_exact[rowA], ford(s));
            qi = qj; haveA = haveB;
            if (haveB) {
                rowA = rowB;
#pragma unroll
                for (int q = 0; q < 4; ++q) { TA[q] = TB[q]; IA[q] = IB[q]; }
            }
        }
    }

    // ---- fallback (never expected): full exact recompute per row
    if (qtotal > QMAX) {
        for (int row = w; row < MROWS; row += 16) {
            const float4* tp = (const float4*)(textf + (size_t)(trow0 + row) * DIM);
            float4 ta[4];
#pragma unroll
            for (int q = 0; q < 4; ++q) ta[q] = tp[q * 32 + l];
            float emax = -INFINITY;
            for (int j = 0; j < ITOK; ++j) {
                const float4* ip = (const float4*)(imgf + ((size_t)b2 * ITOK + j) * DIM);
                float s = 0.0f;
#pragma unroll
                for (int q = 0; q < 4; ++q) {
                    float4 iv = ip[q * 32 + l];
                    s = fmaf(ta[q].x, iv.x, s);
                    s = fmaf(ta[q].y, iv.y, s);
                    s = fmaf(ta[q].z, iv.z, s);
                    s = fmaf(ta[q].w, iv.w, s);
                }
#pragma unroll
                for (int off = 16; off > 0; off >>= 1)
                    s += __shfl_xor_sync(0xffffffffu, s, off);
                emax = fmaxf(emax, s);
            }
            if (l == 0) atomicMax(&s_exact[row], ford(emax));
        }
    }
    __syncthreads();

    // ---- mean over text rows -> g_S
    if (tid < MROWS) {
        float m = funord(s_exact[tid]);
#pragma unroll
        for (int off = 16; off > 0; off >>= 1)
            m += __shfl_xor_sync(0xffffffffu, m, off);
        if ((tid & 31) == 0) s_red[tid >> 5] = m;
    }
    __syncthreads();
    if (tid == 0) {
        g_S[(mtile * 2 + 0) * BATCH + b2] = (s_red[0] + s_red[1]) * (1.0f / TTOK);
        g_S[(mtile * 2 + 1) * BATCH + b2] = (s_red[2] + s_red[3]) * (1.0f / TTOK);
    }
}

// ---------------- symmetric InfoNCE ----------------
__global__ void loss_kernel(float* __restrict__ out) {
    __shared__ float s_red[BATCH];
    __shared__ float s_fin[4];
    const int tid = threadIdx.x;
    const int b = tid >> 3, s = tid & 7;
    const float invT = 1.0f / TEMP;

    float rv[16], cv[16];
#pragma unroll
    for (int j = 0; j < 16; ++j) {
        int jj = s * 16 + j;
        rv[j] = g_S[b * BATCH + jj];
        cv[j] = g_S[jj * BATCH + b];
    }
    float rmax = -INFINITY, cmax = -INFINITY;
#pragma unroll
    for (int j = 0; j < 16; ++j) {
        rmax = fmaxf(rmax, rv[j]);
        cmax = fmaxf(cmax, cv[j]);
    }
#pragma unroll
    for (int off = 1; off <= 4; off <<= 1) {
        rmax = fmaxf(rmax, __shfl_xor_sync(0xffffffffu, rmax, off));
        cmax = fmaxf(cmax, __shfl_xor_sync(0xffffffffu, cmax, off));
    }
    float rs = 0.0f, cs = 0.0f;
#pragma unroll
    for (int j = 0; j < 16; ++j) {
        rs += expf((rv[j] - rmax) * invT);
        cs += expf((cv[j] - cmax) * invT);
    }
#pragma unroll
    for (int off = 1; off <= 4; off <<= 1) {
        rs += __shfl_xor_sync(0xffffffffu, rs, off);
        cs += __shfl_xor_sync(0xffffffffu, cs, off);
    }
    if (s == 0) {
        float diag = g_S[b * BATCH + b] * invT;
        float rlse = rmax * invT + logf(rs);
        float clse = cmax * invT + logf(cs);
        s_red[b] = 0.5f * ((rlse - diag) + (clse - diag));
    }
    __syncthreads();
    if (tid < 128) {
        float v = s_red[tid];
#pragma unroll
        for (int off = 16; off > 0; off >>= 1)
            v += __shfl_xor_sync(0xffffffffu, v, off);
        if ((tid & 31) == 0) s_fin[tid >> 5] = v;
    }
    __syncthreads();
    if (tid == 0)
        out[0] = (s_fin[0] + s_fin[1] + s_fin[2] + s_fin[3]) * (1.0f / BATCH);
}

extern "C" void kernel_launch(void* const* d_in, const int* in_sizes, int n_in,
                              void* d_out, int out_size) {
    const float* image = (const float*)d_in[0];   // [128, 196, 512]
    const float* text  = (const float*)d_in[1];   // [128,  64, 512]

    __half *thi, *ihi;
    cudaGetSymbolAddress((void**)&thi, g_text_hi);
    cudaGetSymbolAddress((void**)&ihi, g_img_hi);

    init_kernel<<<1, 256>>>();
    convert_norm<<<BATCH * TTOK / 4, 512>>>(text, thi, BATCH * TTOK, 0);
    convert_norm<<<BATCH * ITOK / 4, 512>>>(image, ihi, BATCH * ITOK, 1);

    cudaFuncSetAttribute(maxsim_kernel,
                         cudaFuncAttributeMaxDynamicSharedMemorySize, SMEM_BYTES);
    maxsim_kernel<<<dim3(BATCH * TTOK / MROWS, BATCH), NTHREADS, SMEM_BYTES>>>(image, text);

    loss_kernel<<<1, 1024>>>((float*)d_out);
}